// round 2
// baseline (speedup 1.0000x reference)
#include <cuda_runtime.h>
#include <cstdint>

#define Bb   8
#define Tt   4096
#define Dd   768
#define Hh   12
#define HDd  64
#define KSp  32
#define D3   2304

#define NSEG 32
#define TSEG (Tt / NSEG)   // 128

// ---------------- scratch (no allocations allowed) ----------------
__device__ float g_partial[NSEG * Bb * KSp * Dd];   // ~25.2 MB
__device__ float g_xs[Bb * KSp * Dd];               // 786 KB
__device__ float g_qkv[Bb * KSp * D3];              // 2.36 MB
__device__ float g_vg[Bb * KSp * Dd];
__device__ float g_y[Bb * KSp * Dd];

// ---------------- packed f32x2 helpers (FFMA2) ----------------
__device__ __forceinline__ unsigned long long pk2(float lo, float hi) {
    unsigned long long r;
    asm("mov.b64 %0, {%1, %2};" : "=l"(r) : "f"(lo), "f"(hi));
    return r;
}
__device__ __forceinline__ float2 upk2(unsigned long long v) {
    float2 r;
    asm("mov.b64 {%0, %1}, %2;" : "=f"(r.x), "=f"(r.y) : "l"(v));
    return r;
}
__device__ __forceinline__ void fma2(unsigned long long& d,
                                     unsigned long long a,
                                     unsigned long long b) {
    asm("fma.rn.f32x2 %0, %1, %2, %0;" : "+l"(d) : "l"(a), "l"(b));
}

// =====================================================================
// K1: partial[seg][b][k][d] = sum_{t in seg} S[b,t,k] * x[b,t,d]
// grid (NSEG, 3, B), block 128.  Thread: 16 k-rows x 4 d-cols (2 f32x2 pairs).
// =====================================================================
__global__ void __launch_bounds__(128) k_project(const float* __restrict__ x,
                                                 const float* __restrict__ S) {
    const int seg = blockIdx.x;
    const int dch = blockIdx.y;
    const int b   = blockIdx.z;
    const int t0  = seg * TSEG;
    const int c0  = dch * 256;
    const int tid = threadIdx.x;

    __shared__ unsigned long long Ssm[TSEG][KSp];  // dup-packed, 32 KB

    // load S tile: thread tid loads row tid (32 floats), duplicate-pack
    {
        const float4* srow =
            reinterpret_cast<const float4*>(S + ((size_t)b * Tt + t0 + tid) * KSp);
#pragma unroll
        for (int i = 0; i < 8; i++) {
            float4 v = srow[i];
            Ssm[tid][i * 4 + 0] = pk2(v.x, v.x);
            Ssm[tid][i * 4 + 1] = pk2(v.y, v.y);
            Ssm[tid][i * 4 + 2] = pk2(v.z, v.z);
            Ssm[tid][i * 4 + 3] = pk2(v.w, v.w);
        }
    }
    __syncthreads();

    const int kg   = tid >> 6;          // 0..1  -> k range [kg*16, kg*16+16)
    const int lane = tid & 63;          // 0..63 -> cols c..c+3
    const int c    = c0 + lane * 4;

    unsigned long long acc[16][2];
#pragma unroll
    for (int i = 0; i < 16; i++) { acc[i][0] = 0ull; acc[i][1] = 0ull; }

    const float* xp = x + ((size_t)b * Tt + t0) * Dd + c;
    for (int t = 0; t < TSEG; t++) {
        float4 xv = *reinterpret_cast<const float4*>(xp);
        xp += Dd;
        unsigned long long x01 = pk2(xv.x, xv.y);
        unsigned long long x23 = pk2(xv.z, xv.w);
        const unsigned long long* srow = &Ssm[t][kg * 16];
#pragma unroll
        for (int kk = 0; kk < 16; kk++) {
            unsigned long long s2 = srow[kk];
            fma2(acc[kk][0], s2, x01);
            fma2(acc[kk][1], s2, x23);
        }
    }

#pragma unroll
    for (int kk = 0; kk < 16; kk++) {
        int kidx = kg * 16 + kk;
        float2 a0 = upk2(acc[kk][0]);
        float2 a1 = upk2(acc[kk][1]);
        float4 o = make_float4(a0.x, a0.y, a1.x, a1.y);
        *reinterpret_cast<float4*>(
            &g_partial[(((size_t)seg * Bb + b) * KSp + kidx) * Dd + c]) = o;
    }
}

// =====================================================================
// K2: xs = sum over segments of partials
// =====================================================================
__global__ void k_reduce() {
    const int i = blockIdx.x * blockDim.x + threadIdx.x;   // float4 index
    const int stride4 = (Bb * KSp * Dd) / 4;               // 49152
    const float4* p = reinterpret_cast<const float4*>(g_partial);
    float4 s = make_float4(0.f, 0.f, 0.f, 0.f);
#pragma unroll 8
    for (int seg = 0; seg < NSEG; seg++) {
        float4 v = p[(size_t)seg * stride4 + i];
        s.x += v.x; s.y += v.y; s.z += v.z; s.w += v.w;
    }
    reinterpret_cast<float4*>(g_xs)[i] = s;
}

// =====================================================================
// K3/K5: C[256, N] = A[256, 768] * W[N, 768]^T   (both row-major, inner d)
// which=0: A=g_xs, C=g_qkv (N=2304).  which=1: A=g_vg, C=g_y (N=768).
// Block tile 32m x 64n, BK=32, 256 threads, thread tile 2x4.
// =====================================================================
__global__ void __launch_bounds__(256) k_gemm(const float* __restrict__ W,
                                              int N, int which) {
    const float* A = which ? g_vg : g_xs;
    float*       C = which ? g_y : g_qkv;
    const int n0 = blockIdx.x * 64;
    const int m0 = blockIdx.y * 32;
    const int tid = threadIdx.x;
    const int tx = tid & 15;       // n-dir, 4 cols each
    const int ty = tid >> 4;       // m-dir, 2 rows each

    __shared__ float Asm[32][33];  // [d][m], padded
    __shared__ float Bsm[32][64];  // [d][n]

    float acc[2][4];
#pragma unroll
    for (int i = 0; i < 2; i++)
#pragma unroll
        for (int j = 0; j < 4; j++) acc[i][j] = 0.f;

    for (int d0 = 0; d0 < Dd; d0 += 32) {
        // load A tile (32m x 32d)
        {
            int m  = tid >> 3;
            int dq = (tid & 7) * 4;
            float4 v = *reinterpret_cast<const float4*>(
                &A[(size_t)(m0 + m) * Dd + d0 + dq]);
            Asm[dq + 0][m] = v.x; Asm[dq + 1][m] = v.y;
            Asm[dq + 2][m] = v.z; Asm[dq + 3][m] = v.w;
        }
        // load W tile (64n x 32d)
#pragma unroll
        for (int it = 0; it < 2; it++) {
            int n  = (tid >> 3) + it * 32;
            int dq = (tid & 7) * 4;
            float4 v = *reinterpret_cast<const float4*>(
                &W[(size_t)(n0 + n) * Dd + d0 + dq]);
            Bsm[dq + 0][n] = v.x; Bsm[dq + 1][n] = v.y;
            Bsm[dq + 2][n] = v.z; Bsm[dq + 3][n] = v.w;
        }
        __syncthreads();
#pragma unroll
        for (int d = 0; d < 32; d++) {
            float a0 = Asm[d][ty * 2 + 0];
            float a1 = Asm[d][ty * 2 + 1];
            float4 bv = *reinterpret_cast<const float4*>(&Bsm[d][tx * 4]);
            acc[0][0] += a0 * bv.x; acc[0][1] += a0 * bv.y;
            acc[0][2] += a0 * bv.z; acc[0][3] += a0 * bv.w;
            acc[1][0] += a1 * bv.x; acc[1][1] += a1 * bv.y;
            acc[1][2] += a1 * bv.z; acc[1][3] += a1 * bv.w;
        }
        __syncthreads();
    }

#pragma unroll
    for (int r = 0; r < 2; r++) {
        float4 o = make_float4(acc[r][0], acc[r][1], acc[r][2], acc[r][3]);
        *reinterpret_cast<float4*>(
            &C[(size_t)(m0 + ty * 2 + r) * N + n0 + tx * 4]) = o;
    }
}

// =====================================================================
// K4: attn dot + filter + FHN + scale v_spec into g_vg
// one block of 64 threads per (b,h,k); grid = B*H*KS = 3072
// =====================================================================
__global__ void k_fhn(const float* __restrict__ sfilter) {
    const int bid = blockIdx.x;
    const int b = bid / (Hh * KSp);
    const int r = bid % (Hh * KSp);
    const int h = r / KSp;
    const int kidx = r % KSp;
    const int tid = threadIdx.x;   // 0..63

    const float* row = &g_qkv[(size_t)(b * KSp + kidx) * D3];
    float q  = row[h * HDd + tid];
    float kv = row[Dd + h * HDd + tid];
    float p = q * kv;
#pragma unroll
    for (int o = 16; o > 0; o >>= 1) p += __shfl_down_sync(0xffffffffu, p, o);

    __shared__ float red[2];
    __shared__ float fv;
    if ((tid & 31) == 0) red[tid >> 5] = p;
    __syncthreads();
    if (tid == 0) {
        float attn = (red[0] + red[1]) * 0.125f;              // / sqrt(64)
        float filt = 1.f / (1.f + expf(-sfilter[h * 32 + kidx]));
        attn *= filt;
        // FHN (exact reference semantics)
        float a = fabsf(attn);
        float scale = fmaxf(a, 1e-6f);
        float sn = attn / scale;
        float gate = 1.f / (1.f + expf(-(a - 0.5f) * 10.f));
        float I = sn * (0.1f + 0.9f * gate);
        const float alpha = 1.0f / 12.5f;
        const float denom = 1.0f + alpha * 0.8f;
        float v = 0.f, w = 0.f;
#pragma unroll
        for (int s = 0; s < 2; s++) {
            float dv = v - (v * v * v) * (1.f / 3.f) - w + I;
            float vn = v + dv;                                // DT = 1
            float wn = (w + (vn + 0.7f) * alpha) / denom;     // pre-clip vn
            v = fminf(fmaxf(vn, -3.f), 3.f);
            w = fminf(fmaxf(wn, -3.f), 3.f);
        }
        fv = v * scale;
    }
    __syncthreads();
    g_vg[(size_t)(b * KSp + kidx) * Dd + h * HDd + tid] =
        fv * row[2 * Dd + h * HDd + tid];
}

// =====================================================================
// K6: out[b,t,e] = sum_k S[b,t,k] * y[b,k,e]
// grid (T/128, 3, B), block 128. Thread: 2 e-cols, y in regs, FFMA2.
// =====================================================================
__global__ void __launch_bounds__(128) k_expand(const float* __restrict__ S,
                                                float* __restrict__ out) {
    const int tt  = blockIdx.x;
    const int ech = blockIdx.y;
    const int b   = blockIdx.z;
    const int t0  = tt * 128;
    const int e0  = ech * 256;
    const int tid = threadIdx.x;

    __shared__ unsigned long long Ssm[128][KSp];  // dup-packed, 32 KB
    {
        const float4* srow =
            reinterpret_cast<const float4*>(S + ((size_t)b * Tt + t0 + tid) * KSp);
#pragma unroll
        for (int i = 0; i < 8; i++) {
            float4 v = srow[i];
            Ssm[tid][i * 4 + 0] = pk2(v.x, v.x);
            Ssm[tid][i * 4 + 1] = pk2(v.y, v.y);
            Ssm[tid][i * 4 + 2] = pk2(v.z, v.z);
            Ssm[tid][i * 4 + 3] = pk2(v.w, v.w);
        }
    }
    __syncthreads();

    unsigned long long yv[KSp];
#pragma unroll
    for (int kk = 0; kk < KSp; kk++) {
        float2 y2 = *reinterpret_cast<const float2*>(
            &g_y[(size_t)(b * KSp + kk) * Dd + e0 + tid * 2]);
        yv[kk] = pk2(y2.x, y2.y);
    }

    float* op = out + ((size_t)b * Tt + t0) * Dd + e0 + tid * 2;
    for (int tp = 0; tp < 64; tp++) {
        const int ta = tp * 2;
        unsigned long long aA = 0ull, aB = 0ull;
#pragma unroll
        for (int kk = 0; kk < KSp; kk++) {
            fma2(aA, Ssm[ta + 0][kk], yv[kk]);
            fma2(aB, Ssm[ta + 1][kk], yv[kk]);
        }
        *reinterpret_cast<float2*>(op + (size_t)(ta + 0) * Dd) = upk2(aA);
        *reinterpret_cast<float2*>(op + (size_t)(ta + 1) * Dd) = upk2(aB);
    }
}

// =====================================================================
extern "C" void kernel_launch(void* const* d_in, const int* in_sizes, int n_in,
                              void* d_out, int out_size) {
    const float* x       = (const float*)d_in[0];   // [B,T,D]
    const float* S       = (const float*)d_in[1];   // [B,T,K]
    const float* w_qkv   = (const float*)d_in[2];   // [2304,768]
    const float* w_out   = (const float*)d_in[3];   // [768,768]
    const float* sfilter = (const float*)d_in[4];   // [12,32]
    float* out = (float*)d_out;

    k_project<<<dim3(NSEG, 3, Bb), 128>>>(x, S);
    k_reduce<<<192, 256>>>();
    k_gemm<<<dim3(D3 / 64, 256 / 32), 256>>>(w_qkv, D3, 0);
    k_fhn<<<Bb * Hh * KSp, 64>>>(sfilter);
    k_gemm<<<dim3(Dd / 64, 256 / 32), 256>>>(w_out, Dd, 1);
    k_expand<<<dim3(Tt / 128, 3, Bb), 128>>>(S, out);
}

// round 3
// speedup vs baseline: 1.3893x; 1.3893x over previous
#include <cuda_runtime.h>
#include <cstdint>

#define Bb   8
#define Tt   4096
#define Dd   768
#define Hh   12
#define HDd  64
#define KSp  32
#define D3   2304

#define NSEG 16
#define TSEG 256   // t per segment
#define TCH  16    // t per smem chunk

typedef unsigned long long u64;

// ---------------- scratch (no allocations allowed) ----------------
__device__ float g_partial[NSEG * Bb * KSp * Dd];   // 12.6 MB
__device__ float g_xs[Bb * KSp * Dd];
__device__ float g_qkv[Bb * KSp * D3];
__device__ float g_vg[Bb * KSp * Dd];
__device__ float g_y[Bb * KSp * Dd];

// ---------------- packed f32x2 helpers (FFMA2) ----------------
__device__ __forceinline__ u64 pk2(float lo, float hi) {
    u64 r;
    asm("mov.b64 %0, {%1, %2};" : "=l"(r) : "f"(lo), "f"(hi));
    return r;
}
__device__ __forceinline__ void fma2(u64& d, u64 a, u64 b) {
    asm("fma.rn.f32x2 %0, %1, %2, %0;" : "+l"(d) : "l"(a), "l"(b));
}

// =====================================================================
// K1: partial[seg][b][k][d] = sum_{t in seg} S[b,t,k] * x[b,t,d]
// grid (3 d-tiles, NSEG, B), 256 threads. Thread tile: 4k x 8d.
// FMA:other issue ratio 16:11 per t -> fma-pipe bound.
// =====================================================================
__global__ void __launch_bounds__(256) k_project(const float* __restrict__ x,
                                                 const float* __restrict__ S) {
    const int dt  = blockIdx.x;           // 0..2
    const int seg = blockIdx.y;
    const int b   = blockIdx.z;
    const int d0  = dt * 256;
    const int t0  = seg * TSEG;
    const int tid = threadIdx.x;

    __shared__ float Ssm[TSEG][KSp];      // 32 KB
    __shared__ float Xsm[TCH][256];       // 16 KB  (total 48 KB)

    // load S tile: 256 rows x 32 floats = 2048 float4, 8 per thread
    {
        const float4* sg = reinterpret_cast<const float4*>(
            S + ((size_t)b * Tt + t0) * KSp);
        float4* ss = reinterpret_cast<float4*>(&Ssm[0][0]);
#pragma unroll
        for (int i = 0; i < 8; i++) ss[tid + i * 256] = sg[tid + i * 256];
    }

    const int kq = tid >> 5;              // 0..7 (warp-uniform -> S broadcast)
    const int dq = tid & 31;              // 0..31

    u64 acc[4][4];
#pragma unroll
    for (int i = 0; i < 4; i++)
#pragma unroll
        for (int j = 0; j < 4; j++) acc[i][j] = 0ull;

    for (int ch = 0; ch < TSEG / TCH; ch++) {
        __syncthreads();
        // load x chunk: 16 rows x 256 cols = 1024 float4, 4 per thread
        const float4* xg = reinterpret_cast<const float4*>(
            x + ((size_t)b * Tt + t0 + ch * TCH) * Dd + d0);
#pragma unroll
        for (int i = 0; i < 4; i++) {
            int idx = tid + i * 256;
            int r = idx >> 6, c = idx & 63;
            reinterpret_cast<float4*>(&Xsm[r][0])[c] = xg[(size_t)r * (Dd / 4) + c];
        }
        __syncthreads();
#pragma unroll
        for (int t = 0; t < TCH; t++) {
            float4 s4 = *reinterpret_cast<const float4*>(&Ssm[ch * TCH + t][kq * 4]);
            u64 sd0 = pk2(s4.x, s4.x), sd1 = pk2(s4.y, s4.y);
            u64 sd2 = pk2(s4.z, s4.z), sd3 = pk2(s4.w, s4.w);
            ulonglong2 xa = *reinterpret_cast<const ulonglong2*>(&Xsm[t][dq * 4]);
            ulonglong2 xb = *reinterpret_cast<const ulonglong2*>(&Xsm[t][128 + dq * 4]);
            fma2(acc[0][0], sd0, xa.x); fma2(acc[0][1], sd0, xa.y);
            fma2(acc[0][2], sd0, xb.x); fma2(acc[0][3], sd0, xb.y);
            fma2(acc[1][0], sd1, xa.x); fma2(acc[1][1], sd1, xa.y);
            fma2(acc[1][2], sd1, xb.x); fma2(acc[1][3], sd1, xb.y);
            fma2(acc[2][0], sd2, xa.x); fma2(acc[2][1], sd2, xa.y);
            fma2(acc[2][2], sd2, xb.x); fma2(acc[2][3], sd2, xb.y);
            fma2(acc[3][0], sd3, xa.x); fma2(acc[3][1], sd3, xa.y);
            fma2(acc[3][2], sd3, xb.x); fma2(acc[3][3], sd3, xb.y);
        }
    }

#pragma unroll
    for (int kk = 0; kk < 4; kk++) {
        float* base = &g_partial[(((size_t)seg * Bb + b) * KSp + kq * 4 + kk) * Dd + d0];
        ulonglong2 o1, o2;
        o1.x = acc[kk][0]; o1.y = acc[kk][1];
        o2.x = acc[kk][2]; o2.y = acc[kk][3];
        *reinterpret_cast<ulonglong2*>(base + dq * 4) = o1;
        *reinterpret_cast<ulonglong2*>(base + 128 + dq * 4) = o2;
    }
}

// =====================================================================
// K2: xs = sum over segments of partials
// =====================================================================
__global__ void k_reduce() {
    const int i = blockIdx.x * blockDim.x + threadIdx.x;   // float4 index
    const int stride4 = (Bb * KSp * Dd) / 4;               // 49152
    const float4* p = reinterpret_cast<const float4*>(g_partial);
    float4 s = make_float4(0.f, 0.f, 0.f, 0.f);
#pragma unroll
    for (int seg = 0; seg < NSEG; seg++) {
        float4 v = p[(size_t)seg * stride4 + i];
        s.x += v.x; s.y += v.y; s.z += v.z; s.w += v.w;
    }
    reinterpret_cast<float4*>(g_xs)[i] = s;
}

// =====================================================================
// K3/K5: C[256, N] = A[256, 768] * W[N, 768]^T
// =====================================================================
__global__ void __launch_bounds__(256) k_gemm(const float* __restrict__ W,
                                              int N, int which) {
    const float* A = which ? g_vg : g_xs;
    float*       C = which ? g_y : g_qkv;
    const int n0 = blockIdx.x * 64;
    const int m0 = blockIdx.y * 32;
    const int tid = threadIdx.x;
    const int tx = tid & 15;
    const int ty = tid >> 4;

    __shared__ float Asm[32][33];
    __shared__ float Bsm[32][64];

    float acc[2][4];
#pragma unroll
    for (int i = 0; i < 2; i++)
#pragma unroll
        for (int j = 0; j < 4; j++) acc[i][j] = 0.f;

    for (int d0 = 0; d0 < Dd; d0 += 32) {
        {
            int m  = tid >> 3;
            int dq = (tid & 7) * 4;
            float4 v = *reinterpret_cast<const float4*>(
                &A[(size_t)(m0 + m) * Dd + d0 + dq]);
            Asm[dq + 0][m] = v.x; Asm[dq + 1][m] = v.y;
            Asm[dq + 2][m] = v.z; Asm[dq + 3][m] = v.w;
        }
#pragma unroll
        for (int it = 0; it < 2; it++) {
            int n  = (tid >> 3) + it * 32;
            int dq = (tid & 7) * 4;
            float4 v = *reinterpret_cast<const float4*>(
                &W[(size_t)(n0 + n) * Dd + d0 + dq]);
            Bsm[dq + 0][n] = v.x; Bsm[dq + 1][n] = v.y;
            Bsm[dq + 2][n] = v.z; Bsm[dq + 3][n] = v.w;
        }
        __syncthreads();
#pragma unroll
        for (int d = 0; d < 32; d++) {
            float a0 = Asm[d][ty * 2 + 0];
            float a1 = Asm[d][ty * 2 + 1];
            float4 bv = *reinterpret_cast<const float4*>(&Bsm[d][tx * 4]);
            acc[0][0] += a0 * bv.x; acc[0][1] += a0 * bv.y;
            acc[0][2] += a0 * bv.z; acc[0][3] += a0 * bv.w;
            acc[1][0] += a1 * bv.x; acc[1][1] += a1 * bv.y;
            acc[1][2] += a1 * bv.z; acc[1][3] += a1 * bv.w;
        }
        __syncthreads();
    }

#pragma unroll
    for (int r = 0; r < 2; r++) {
        float4 o = make_float4(acc[r][0], acc[r][1], acc[r][2], acc[r][3]);
        *reinterpret_cast<float4*>(
            &C[(size_t)(m0 + ty * 2 + r) * N + n0 + tx * 4]) = o;
    }
}

// =====================================================================
// K4: one warp per (b,h,k): dot(q,k) + filter + FHN + scale v
// grid 384 blocks x 256 threads (8 warps each)
// =====================================================================
__global__ void __launch_bounds__(256) k_fhn(const float* __restrict__ sfilter) {
    const int tid  = threadIdx.x;
    const int lane = tid & 31;
    const int idx  = blockIdx.x * 8 + (tid >> 5);   // 0..3071
    const int b    = idx / (Hh * KSp);
    const int r    = idx % (Hh * KSp);
    const int h    = r >> 5;
    const int kidx = r & 31;

    const float* row = &g_qkv[(size_t)(b * KSp + kidx) * D3];
    float2 q  = *reinterpret_cast<const float2*>(row + h * HDd + lane * 2);
    float2 kv = *reinterpret_cast<const float2*>(row + Dd + h * HDd + lane * 2);
    float p = q.x * kv.x + q.y * kv.y;
#pragma unroll
    for (int o = 16; o; o >>= 1) p += __shfl_xor_sync(0xffffffffu, p, o);

    float attn = p * 0.125f;                          // / sqrt(64)
    float filt = 1.f / (1.f + expf(-sfilter[h * 32 + kidx]));
    attn *= filt;

    float a = fabsf(attn);
    float scale = fmaxf(a, 1e-6f);
    float sn = attn / scale;
    float gate = 1.f / (1.f + expf(-(a - 0.5f) * 10.f));
    float I = sn * (0.1f + 0.9f * gate);
    const float alpha = 1.0f / 12.5f;
    const float denom = 1.0f + alpha * 0.8f;
    float v = 0.f, w = 0.f;
#pragma unroll
    for (int s = 0; s < 2; s++) {
        float dv = v - (v * v * v) * (1.f / 3.f) - w + I;
        float vn = v + dv;
        float wn = (w + (vn + 0.7f) * alpha) / denom;
        v = fminf(fmaxf(vn, -3.f), 3.f);
        w = fminf(fmaxf(wn, -3.f), 3.f);
    }
    float fv = v * scale;

    float2 vs = *reinterpret_cast<const float2*>(row + 2 * Dd + h * HDd + lane * 2);
    *reinterpret_cast<float2*>(&g_vg[(size_t)(b * KSp + kidx) * Dd + h * HDd + lane * 2]) =
        make_float2(fv * vs.x, fv * vs.y);
}

// =====================================================================
// K6: out[b, t0:t0+128, e0:e0+128] = S[b, t-tile, :] * y[b, :, e-tile]
// K=32 fully unrolled, thread tile 8t x 8e, FFMA2.
// =====================================================================
__global__ void __launch_bounds__(256, 2) k_expand(const float* __restrict__ S,
                                                   float* __restrict__ out) {
    const int et  = blockIdx.x;   // 0..5
    const int tt  = blockIdx.y;   // 0..31
    const int b   = blockIdx.z;
    const int e0  = et * 128;
    const int t0  = tt * 128;
    const int tid = threadIdx.x;

    __shared__ float Ssm[128][KSp];   // 16 KB
    __shared__ float Ysm[KSp][128];   // 16 KB

    {
        const float4* sg = reinterpret_cast<const float4*>(
            S + ((size_t)b * Tt + t0) * KSp);
        float4* ss = reinterpret_cast<float4*>(&Ssm[0][0]);
#pragma unroll
        for (int i = 0; i < 4; i++) ss[tid + i * 256] = sg[tid + i * 256];
#pragma unroll
        for (int i = 0; i < 4; i++) {
            int idx = tid + i * 256;
            int r = idx >> 5, c = idx & 31;
            reinterpret_cast<float4*>(&Ysm[r][0])[c] =
                *reinterpret_cast<const float4*>(
                    &g_y[((size_t)b * KSp + r) * Dd + e0 + c * 4]);
        }
    }
    __syncthreads();

    const int i0 = (tid >> 4) * 8;   // t rows
    const int j0 = tid & 15;         // e col group

    u64 acc[8][4];
#pragma unroll
    for (int i = 0; i < 8; i++)
#pragma unroll
        for (int j = 0; j < 4; j++) acc[i][j] = 0ull;

#pragma unroll
    for (int k = 0; k < KSp; k++) {
        ulonglong2 ya = *reinterpret_cast<const ulonglong2*>(&Ysm[k][j0 * 4]);
        ulonglong2 yb = *reinterpret_cast<const ulonglong2*>(&Ysm[k][64 + j0 * 4]);
#pragma unroll
        for (int i = 0; i < 8; i++) {
            float sv = Ssm[i0 + i][k];
            u64 sd = pk2(sv, sv);
            fma2(acc[i][0], sd, ya.x); fma2(acc[i][1], sd, ya.y);
            fma2(acc[i][2], sd, yb.x); fma2(acc[i][3], sd, yb.y);
        }
    }

    float* ob = out + ((size_t)b * Tt + t0 + i0) * Dd + e0;
#pragma unroll
    for (int i = 0; i < 8; i++) {
        ulonglong2 o1, o2;
        o1.x = acc[i][0]; o1.y = acc[i][1];
        o2.x = acc[i][2]; o2.y = acc[i][3];
        *reinterpret_cast<ulonglong2*>(ob + (size_t)i * Dd + j0 * 4) = o1;
        *reinterpret_cast<ulonglong2*>(ob + (size_t)i * Dd + 64 + j0 * 4) = o2;
    }
}

// =====================================================================
extern "C" void kernel_launch(void* const* d_in, const int* in_sizes, int n_in,
                              void* d_out, int out_size) {
    const float* x       = (const float*)d_in[0];   // [B,T,D]
    const float* S       = (const float*)d_in[1];   // [B,T,K]
    const float* w_qkv   = (const float*)d_in[2];   // [2304,768]
    const float* w_out   = (const float*)d_in[3];   // [768,768]
    const float* sfilter = (const float*)d_in[4];   // [12,32]
    float* out = (float*)d_out;

    k_project<<<dim3(3, NSEG, Bb), 256>>>(x, S);
    k_reduce<<<192, 256>>>();
    k_gemm<<<dim3(D3 / 64, 256 / 32), 256>>>(w_qkv, D3, 0);
    k_fhn<<<384, 256>>>(sfilter);
    k_gemm<<<dim3(Dd / 64, 256 / 32), 256>>>(w_out, Dd, 1);
    k_expand<<<dim3(6, 32, Bb), 256>>>(S, out);
}

// round 4
// speedup vs baseline: 1.7780x; 1.2797x over previous
#include <cuda_runtime.h>
#include <cstdint>

#define Bb   8
#define Tt   4096
#define Dd   768
#define Hh   12
#define HDd  64
#define KSp  32
#define D3   2304

#define NSEG 16
#define TSEG 256
#define TCH  16

typedef unsigned long long u64;

// ---------------- scratch ----------------
__device__ float g_partial[NSEG * Bb * KSp * Dd];
__device__ float g_xs[Bb * KSp * Dd];
__device__ float g_qkv[Bb * KSp * D3];
__device__ float g_y[Bb * KSp * Dd];

// ---------------- packed f32x2 ----------------
__device__ __forceinline__ u64 pk2(float lo, float hi) {
    u64 r;
    asm("mov.b64 %0, {%1, %2};" : "=l"(r) : "f"(lo), "f"(hi));
    return r;
}
__device__ __forceinline__ void fma2(u64& d, u64 a, u64 b) {
    asm("fma.rn.f32x2 %0, %1, %2, %0;" : "+l"(d) : "l"(a), "l"(b));
}

__global__ void k_nop() {}

// =====================================================================
// K1: partial[seg][b][k][d] = sum_{t in seg} S[b,t,k] * x[b,t,d]
// grid (3, NSEG, B), 256 thr, thread tile 4k x 8d, register-prefetched.
// =====================================================================
__global__ void __launch_bounds__(256, 3) k_project(const float* __restrict__ x,
                                                    const float* __restrict__ S) {
    const int d0  = blockIdx.x * 256;
    const int t0  = blockIdx.y * TSEG;
    const int b   = blockIdx.z;
    const int tid = threadIdx.x;

    __shared__ float Ssm[TSEG][KSp];   // 32 KB
    __shared__ float Xsm[TCH][256];    // 16 KB

    const float* xbase = x + ((size_t)b * Tt + t0) * Dd + d0;
    const int lr = tid >> 6;           // 0..3
    const int lc = tid & 63;           // 0..63

    // prefetch x chunk 0 into registers (LDGs in flight during S copy)
    float4 xr[4];
#pragma unroll
    for (int i = 0; i < 4; i++)
        xr[i] = *reinterpret_cast<const float4*>(
            xbase + (size_t)(lr + i * 4) * Dd + lc * 4);

    // S tile: 256 x 32 floats
    {
        const float4* sg = reinterpret_cast<const float4*>(
            S + ((size_t)b * Tt + t0) * KSp);
        float4* ss = reinterpret_cast<float4*>(&Ssm[0][0]);
#pragma unroll
        for (int i = 0; i < 8; i++) ss[tid + i * 256] = sg[tid + i * 256];
    }

    const int kq = tid >> 5;           // warp-uniform -> S broadcast
    const int dq = tid & 31;

    u64 acc[4][4];
#pragma unroll
    for (int i = 0; i < 4; i++)
#pragma unroll
        for (int j = 0; j < 4; j++) acc[i][j] = 0ull;

    for (int ch = 0; ch < TSEG / TCH; ch++) {
        // commit staged chunk to smem
#pragma unroll
        for (int i = 0; i < 4; i++)
            *reinterpret_cast<float4*>(&Xsm[lr + i * 4][lc * 4]) = xr[i];
        __syncthreads();
        // prefetch next chunk (latency hides behind compute below)
        if (ch + 1 < TSEG / TCH) {
            const float* nb = xbase + (size_t)(ch + 1) * TCH * Dd;
#pragma unroll
            for (int i = 0; i < 4; i++)
                xr[i] = *reinterpret_cast<const float4*>(
                    nb + (size_t)(lr + i * 4) * Dd + lc * 4);
        }
#pragma unroll
        for (int t = 0; t < TCH; t++) {
            float4 s4 = *reinterpret_cast<const float4*>(&Ssm[ch * TCH + t][kq * 4]);
            u64 sd0 = pk2(s4.x, s4.x), sd1 = pk2(s4.y, s4.y);
            u64 sd2 = pk2(s4.z, s4.z), sd3 = pk2(s4.w, s4.w);
            ulonglong2 xa = *reinterpret_cast<const ulonglong2*>(&Xsm[t][dq * 4]);
            ulonglong2 xb = *reinterpret_cast<const ulonglong2*>(&Xsm[t][128 + dq * 4]);
            fma2(acc[0][0], sd0, xa.x); fma2(acc[0][1], sd0, xa.y);
            fma2(acc[0][2], sd0, xb.x); fma2(acc[0][3], sd0, xb.y);
            fma2(acc[1][0], sd1, xa.x); fma2(acc[1][1], sd1, xa.y);
            fma2(acc[1][2], sd1, xb.x); fma2(acc[1][3], sd1, xb.y);
            fma2(acc[2][0], sd2, xa.x); fma2(acc[2][1], sd2, xa.y);
            fma2(acc[2][2], sd2, xb.x); fma2(acc[2][3], sd2, xb.y);
            fma2(acc[3][0], sd3, xa.x); fma2(acc[3][1], sd3, xa.y);
            fma2(acc[3][2], sd3, xb.x); fma2(acc[3][3], sd3, xb.y);
        }
        __syncthreads();
    }

#pragma unroll
    for (int kk = 0; kk < 4; kk++) {
        float* base = &g_partial[(((size_t)blockIdx.y * Bb + b) * KSp + kq * 4 + kk) * Dd + d0];
        ulonglong2 o1, o2;
        o1.x = acc[kk][0]; o1.y = acc[kk][1];
        o2.x = acc[kk][2]; o2.y = acc[kk][3];
        *reinterpret_cast<ulonglong2*>(base + dq * 4) = o1;
        *reinterpret_cast<ulonglong2*>(base + 128 + dq * 4) = o2;
    }
}

// =====================================================================
// K2: xs = sum over segments
// =====================================================================
__global__ void k_reduce() {
    const int i = blockIdx.x * blockDim.x + threadIdx.x;
    const int stride4 = (Bb * KSp * Dd) / 4;
    const float4* p = reinterpret_cast<const float4*>(g_partial);
    float4 s = make_float4(0.f, 0.f, 0.f, 0.f);
#pragma unroll
    for (int seg = 0; seg < NSEG; seg++) {
        float4 v = p[(size_t)seg * stride4 + i];
        s.x += v.x; s.y += v.y; s.z += v.z; s.w += v.w;
    }
    reinterpret_cast<float4*>(g_xs)[i] = s;
}

// =====================================================================
// K3: qkv[256,2304] = xs[256,768] * w_qkv[2304,768]^T
// tiles 64m x 64n, BK=32, 256 thr, thread tile 4m x 4n (FFMA2), prefetched.
// =====================================================================
__global__ void __launch_bounds__(256) k_gemm1(const float* __restrict__ W) {
    const int n0 = blockIdx.x * 64;
    const int m0 = blockIdx.y * 64;
    const int tid = threadIdx.x;
    const int tn = tid & 15, tm = tid >> 4;
    const int lr = tid >> 3, lc = tid & 7;

    __shared__ float Asm[32][68];
    __shared__ float Bsm[32][68];

    float4 ar[2], br[2];
#pragma unroll
    for (int i = 0; i < 2; i++) {
        ar[i] = *reinterpret_cast<const float4*>(
            &g_xs[(size_t)(m0 + lr + i * 32) * Dd + lc * 4]);
        br[i] = *reinterpret_cast<const float4*>(
            &W[(size_t)(n0 + lr + i * 32) * Dd + lc * 4]);
    }

    u64 acc[4][2];
#pragma unroll
    for (int r = 0; r < 4; r++) { acc[r][0] = 0ull; acc[r][1] = 0ull; }

    for (int d0 = 0; d0 < Dd; d0 += 32) {
#pragma unroll
        for (int i = 0; i < 2; i++) {
            int r = lr + i * 32;
            Asm[lc * 4 + 0][r] = ar[i].x; Asm[lc * 4 + 1][r] = ar[i].y;
            Asm[lc * 4 + 2][r] = ar[i].z; Asm[lc * 4 + 3][r] = ar[i].w;
            Bsm[lc * 4 + 0][r] = br[i].x; Bsm[lc * 4 + 1][r] = br[i].y;
            Bsm[lc * 4 + 2][r] = br[i].z; Bsm[lc * 4 + 3][r] = br[i].w;
        }
        __syncthreads();
        if (d0 + 32 < Dd) {
#pragma unroll
            for (int i = 0; i < 2; i++) {
                ar[i] = *reinterpret_cast<const float4*>(
                    &g_xs[(size_t)(m0 + lr + i * 32) * Dd + d0 + 32 + lc * 4]);
                br[i] = *reinterpret_cast<const float4*>(
                    &W[(size_t)(n0 + lr + i * 32) * Dd + d0 + 32 + lc * 4]);
            }
        }
#pragma unroll
        for (int k = 0; k < 32; k++) {
            float4 av = *reinterpret_cast<const float4*>(&Asm[k][tm * 4]);
            ulonglong2 bv = *reinterpret_cast<const ulonglong2*>(&Bsm[k][tn * 4]);
            u64 a0 = pk2(av.x, av.x), a1 = pk2(av.y, av.y);
            u64 a2 = pk2(av.z, av.z), a3 = pk2(av.w, av.w);
            fma2(acc[0][0], a0, bv.x); fma2(acc[0][1], a0, bv.y);
            fma2(acc[1][0], a1, bv.x); fma2(acc[1][1], a1, bv.y);
            fma2(acc[2][0], a2, bv.x); fma2(acc[2][1], a2, bv.y);
            fma2(acc[3][0], a3, bv.x); fma2(acc[3][1], a3, bv.y);
        }
        __syncthreads();
    }

#pragma unroll
    for (int r = 0; r < 4; r++) {
        ulonglong2 o; o.x = acc[r][0]; o.y = acc[r][1];
        *reinterpret_cast<ulonglong2*>(
            &g_qkv[(size_t)(m0 + tm * 4 + r) * D3 + n0 + tn * 4]) = o;
    }
}

// =====================================================================
// K4: fused FHN + gemm2:  y[256,768] = (fv ⊙ v_spec) * w_out^T
// grid (12 n-tiles, 8 b), 128 thr. Prologue computes fv[32][12] per block.
// =====================================================================
__global__ void __launch_bounds__(128) k_gemm2(const float* __restrict__ W,
                                               const float* __restrict__ sfilter) {
    const int n0 = blockIdx.x * 64;
    const int bb = blockIdx.y;
    const int tid = threadIdx.x;
    const int tn = tid & 15, tm = tid >> 4;   // tm 0..7
    const int lr = tid >> 3, lc = tid & 7;    // lr 0..15

    __shared__ float Asm[32][36];
    __shared__ float Bsm[32][68];
    __shared__ float fvs[KSp][Hh];

    // ---- FHN prologue: 384 (m,h) pairs over 128 threads ----
#pragma unroll
    for (int p = 0; p < 3; p++) {
        int idx = tid + p * 128;
        int m = idx & 31, h = idx >> 5;
        const float4* qp = reinterpret_cast<const float4*>(
            g_qkv + (size_t)(bb * KSp + m) * D3 + h * HDd);
        const float4* kp = reinterpret_cast<const float4*>(
            g_qkv + (size_t)(bb * KSp + m) * D3 + Dd + h * HDd);
        float s = 0.f;
#pragma unroll
        for (int j = 0; j < 16; j++) {
            float4 a = qp[j], c = kp[j];
            s += a.x * c.x + a.y * c.y + a.z * c.z + a.w * c.w;
        }
        float filt = 1.f / (1.f + expf(-sfilter[h * 32 + m]));
        float attn = s * 0.125f * filt;

        float aa = fabsf(attn);
        float scale = fmaxf(aa, 1e-6f);
        float sn = attn / scale;
        float gate = 1.f / (1.f + expf(-(aa - 0.5f) * 10.f));
        float I = sn * (0.1f + 0.9f * gate);
        const float alpha = 1.0f / 12.5f;
        const float denom = 1.0f + alpha * 0.8f;
        float v = 0.f, w = 0.f;
#pragma unroll
        for (int st = 0; st < 2; st++) {
            float dv = v - (v * v * v) * (1.f / 3.f) - w + I;
            float vn = v + dv;
            float wn = (w + (vn + 0.7f) * alpha) / denom;
            v = fminf(fmaxf(vn, -3.f), 3.f);
            w = fminf(fmaxf(wn, -3.f), 3.f);
        }
        fvs[m][h] = v * scale;
    }

    // ---- prefetch first tiles ----
    float4 ar[2], br[4];
#pragma unroll
    for (int i = 0; i < 2; i++)
        ar[i] = *reinterpret_cast<const float4*>(
            &g_qkv[(size_t)(bb * KSp + lr + i * 16) * D3 + 2 * Dd + lc * 4]);
#pragma unroll
    for (int i = 0; i < 4; i++)
        br[i] = *reinterpret_cast<const float4*>(
            &W[(size_t)(n0 + lr + i * 16) * Dd + lc * 4]);
    __syncthreads();   // fvs visible before STS uses it

    u64 acc[4][2];
#pragma unroll
    for (int r = 0; r < 4; r++) { acc[r][0] = 0ull; acc[r][1] = 0ull; }

    for (int d0 = 0; d0 < Dd; d0 += 32) {
        const int hh = d0 >> 6;
#pragma unroll
        for (int i = 0; i < 2; i++) {
            int r = lr + i * 16;
            float f = fvs[r][hh];
            Asm[lc * 4 + 0][r] = ar[i].x * f; Asm[lc * 4 + 1][r] = ar[i].y * f;
            Asm[lc * 4 + 2][r] = ar[i].z * f; Asm[lc * 4 + 3][r] = ar[i].w * f;
        }
#pragma unroll
        for (int i = 0; i < 4; i++) {
            int r = lr + i * 16;
            Bsm[lc * 4 + 0][r] = br[i].x; Bsm[lc * 4 + 1][r] = br[i].y;
            Bsm[lc * 4 + 2][r] = br[i].z; Bsm[lc * 4 + 3][r] = br[i].w;
        }
        __syncthreads();
        if (d0 + 32 < Dd) {
#pragma unroll
            for (int i = 0; i < 2; i++)
                ar[i] = *reinterpret_cast<const float4*>(
                    &g_qkv[(size_t)(bb * KSp + lr + i * 16) * D3 + 2 * Dd + d0 + 32 + lc * 4]);
#pragma unroll
            for (int i = 0; i < 4; i++)
                br[i] = *reinterpret_cast<const float4*>(
                    &W[(size_t)(n0 + lr + i * 16) * Dd + d0 + 32 + lc * 4]);
        }
#pragma unroll
        for (int k = 0; k < 32; k++) {
            float4 av = *reinterpret_cast<const float4*>(&Asm[k][tm * 4]);
            ulonglong2 bv = *reinterpret_cast<const ulonglong2*>(&Bsm[k][tn * 4]);
            u64 a0 = pk2(av.x, av.x), a1 = pk2(av.y, av.y);
            u64 a2 = pk2(av.z, av.z), a3 = pk2(av.w, av.w);
            fma2(acc[0][0], a0, bv.x); fma2(acc[0][1], a0, bv.y);
            fma2(acc[1][0], a1, bv.x); fma2(acc[1][1], a1, bv.y);
            fma2(acc[2][0], a2, bv.x); fma2(acc[2][1], a2, bv.y);
            fma2(acc[3][0], a3, bv.x); fma2(acc[3][1], a3, bv.y);
        }
        __syncthreads();
    }

#pragma unroll
    for (int r = 0; r < 4; r++) {
        ulonglong2 o; o.x = acc[r][0]; o.y = acc[r][1];
        *reinterpret_cast<ulonglong2*>(
            &g_y[(size_t)(bb * KSp + tm * 4 + r) * Dd + n0 + tn * 4]) = o;
    }
}

// =====================================================================
// K5: out tile [128t x 128e] = S[b,t-tile,:] * y[b,:,e-tile]
// =====================================================================
__global__ void __launch_bounds__(256, 2) k_expand(const float* __restrict__ S,
                                                   float* __restrict__ out) {
    const int e0  = blockIdx.x * 128;
    const int t0  = blockIdx.y * 128;
    const int b   = blockIdx.z;
    const int tid = threadIdx.x;

    __shared__ float Ssm[128][KSp];
    __shared__ float Ysm[KSp][128];

    {
        const float4* sg = reinterpret_cast<const float4*>(
            S + ((size_t)b * Tt + t0) * KSp);
        float4* ss = reinterpret_cast<float4*>(&Ssm[0][0]);
#pragma unroll
        for (int i = 0; i < 4; i++) ss[tid + i * 256] = sg[tid + i * 256];
#pragma unroll
        for (int i = 0; i < 4; i++) {
            int idx = tid + i * 256;
            int r = idx >> 5, c = idx & 31;
            reinterpret_cast<float4*>(&Ysm[r][0])[c] =
                *reinterpret_cast<const float4*>(
                    &g_y[((size_t)b * KSp + r) * Dd + e0 + c * 4]);
        }
    }
    __syncthreads();

    const int i0 = (tid >> 4) * 8;
    const int j0 = tid & 15;

    u64 acc[8][4];
#pragma unroll
    for (int i = 0; i < 8; i++)
#pragma unroll
        for (int j = 0; j < 4; j++) acc[i][j] = 0ull;

#pragma unroll
    for (int k = 0; k < KSp; k++) {
        ulonglong2 ya = *reinterpret_cast<const ulonglong2*>(&Ysm[k][j0 * 4]);
        ulonglong2 yb = *reinterpret_cast<const ulonglong2*>(&Ysm[k][64 + j0 * 4]);
#pragma unroll
        for (int i = 0; i < 8; i++) {
            float sv = Ssm[i0 + i][k];
            u64 sd = pk2(sv, sv);
            fma2(acc[i][0], sd, ya.x); fma2(acc[i][1], sd, ya.y);
            fma2(acc[i][2], sd, yb.x); fma2(acc[i][3], sd, yb.y);
        }
    }

    float* ob = out + ((size_t)b * Tt + t0 + i0) * Dd + e0;
#pragma unroll
    for (int i = 0; i < 8; i++) {
        ulonglong2 o1, o2;
        o1.x = acc[i][0]; o1.y = acc[i][1];
        o2.x = acc[i][2]; o2.y = acc[i][3];
        *reinterpret_cast<ulonglong2*>(ob + (size_t)i * Dd + j0 * 4) = o1;
        *reinterpret_cast<ulonglong2*>(ob + (size_t)i * Dd + 64 + j0 * 4) = o2;
    }
}

// =====================================================================
extern "C" void kernel_launch(void* const* d_in, const int* in_sizes, int n_in,
                              void* d_out, int out_size) {
    const float* x       = (const float*)d_in[0];
    const float* S       = (const float*)d_in[1];
    const float* w_qkv   = (const float*)d_in[2];
    const float* w_out   = (const float*)d_in[3];
    const float* sfilter = (const float*)d_in[4];
    float* out = (float*)d_out;

    // 3 no-ops so the profiler's fixed capture slot (launch #4) lands on k_project
    k_nop<<<1, 32>>>();
    k_nop<<<1, 32>>>();
    k_nop<<<1, 32>>>();
    k_project<<<dim3(3, NSEG, Bb), 256>>>(x, S);
    k_reduce<<<192, 256>>>();
    k_gemm1<<<dim3(D3 / 64, 4), 256>>>(w_qkv);
    k_gemm2<<<dim3(Dd / 64, Bb), 128>>>(w_out, sfilter);
    k_expand<<<dim3(6, 32, Bb), 256>>>(S, out);
}